// round 16
// baseline (speedup 1.0000x reference)
#include <cuda_runtime.h>
#include <cuda_bf16.h>
#include <cstdint>

// STFT (real part only): n_fft=7, hop=2, win_len=6 (w_pad[6]=0), onesided n_freq=4.
// ABI ground truth (rounds 9-14):
//   d_in[0] = x, 32,000,000 float32  ([64, 500000])
//   d_in[1] = w, 6 float32
//   d_out   = 63,999,232 float32 ([64,4,249997]) -- real part of the STFT.
// out[b][k][f] = sum_{n=0..5} x[b,2f+n]*w[n]*cos(2*pi*n*k/7)
//
// R16: R14 structure (coalesced STG.32 + __stcs, 3x LDG.64/frame, guard-free
// fast path) with FPT=8 to double per-thread MLP and push DRAM utilization.
// R15's shuffle experiment reverted (SHFL shares the MIO pipe -> regression).

namespace {

constexpr int NFREQ = 4;
constexpr int Bc    = 64;
constexpr int FPT   = 8;               // frames per thread
constexpr int TPB   = 256;
constexpr int TILE  = TPB * FPT;       // 2048 frames per block

__global__ __launch_bounds__(TPB)
void stft_re_kernel(const float* __restrict__ x,
                    const float* __restrict__ w,
                    float* __restrict__ out,
                    int L, int F,
                    int fullF,     // == F when geometry exact (fast path), else 0
                    int fcap)      // float store cap for guarded path
{
    // cos(2*pi*(n*k mod 7)/7) for k=1..3, n=1..5 (n=0 -> 1; n=6 unused).
    const float C1[5] = { 0.623489802f, -0.222520934f, -0.900968868f, -0.900968868f, -0.222520934f };
    const float C2[5] = {-0.222520934f, -0.900968868f,  0.623489802f,  0.623489802f, -0.900968868f };
    const float C3[5] = {-0.900968868f,  0.623489802f, -0.222520934f, -0.222520934f,  0.623489802f };

    const int tid = threadIdx.x;
    const int b   = blockIdx.y;
    const int F0  = blockIdx.x * TILE;

    float wv[6];
    #pragma unroll
    for (int n = 0; n < 6; n++) wv[n] = w[n];

    const float2* __restrict__ X2 = reinterpret_cast<const float2*>(x) + (size_t)b * (size_t)(L >> 1);
    float* __restrict__ ob        = out + (size_t)b * (size_t)(NFREQ * F);

    if (F0 + TILE <= fullF) {
        // ---- fast path: no guards anywhere ----
        #pragma unroll
        for (int j = 0; j < FPT; j++) {
            const int f = F0 + j * TPB + tid;        // warp-consecutive frames

            const float2 a = __ldg(X2 + f);
            const float2 c = __ldg(X2 + f + 1);
            const float2 e = __ldg(X2 + f + 2);

            const float y0 = a.x * wv[0];
            const float y1 = a.y * wv[1];
            const float y2 = c.x * wv[2];
            const float y3 = c.y * wv[3];
            const float y4 = e.x * wv[4];
            const float y5 = e.y * wv[5];

            const float r0 = ((y0 + y1) + (y2 + y3)) + (y4 + y5);
            float r1 = y0, r2 = y0, r3 = y0;
            r1 = fmaf(y1, C1[0], r1);  r2 = fmaf(y1, C2[0], r2);  r3 = fmaf(y1, C3[0], r3);
            r1 = fmaf(y2, C1[1], r1);  r2 = fmaf(y2, C2[1], r2);  r3 = fmaf(y2, C3[1], r3);
            r1 = fmaf(y3, C1[2], r1);  r2 = fmaf(y3, C2[2], r2);  r3 = fmaf(y3, C3[2], r3);
            r1 = fmaf(y4, C1[3], r1);  r2 = fmaf(y4, C2[3], r2);  r3 = fmaf(y4, C3[3], r3);
            r1 = fmaf(y5, C1[4], r1);  r2 = fmaf(y5, C2[4], r2);  r3 = fmaf(y5, C3[4], r3);

            float* p = ob + f;
            __stcs(p, r0);  p += F;
            __stcs(p, r1);  p += F;
            __stcs(p, r2);  p += F;
            __stcs(p, r3);
        }
    } else {
        // ---- guarded path (tail block; whole grid if ABI mismatch) ----
        #pragma unroll
        for (int j = 0; j < FPT; j++) {
            const int f = F0 + j * TPB + tid;
            if (f >= F) continue;

            const float2 a = __ldg(X2 + f);
            const float2 c = __ldg(X2 + f + 1);   // floats <= 2(F-1)+3 < L
            const float2 e = __ldg(X2 + f + 2);   // floats <= 2(F-1)+5 < L

            const float y0 = a.x * wv[0];
            const float y1 = a.y * wv[1];
            const float y2 = c.x * wv[2];
            const float y3 = c.y * wv[3];
            const float y4 = e.x * wv[4];
            const float y5 = e.y * wv[5];

            const float r0 = ((y0 + y1) + (y2 + y3)) + (y4 + y5);
            float r1 = y0, r2 = y0, r3 = y0;
            r1 = fmaf(y1, C1[0], r1);  r2 = fmaf(y1, C2[0], r2);  r3 = fmaf(y1, C3[0], r3);
            r1 = fmaf(y2, C1[1], r1);  r2 = fmaf(y2, C2[1], r2);  r3 = fmaf(y2, C3[1], r3);
            r1 = fmaf(y3, C1[2], r1);  r2 = fmaf(y3, C2[2], r2);  r3 = fmaf(y3, C3[2], r3);
            r1 = fmaf(y4, C1[3], r1);  r2 = fmaf(y4, C2[3], r2);  r3 = fmaf(y4, C3[3], r3);
            r1 = fmaf(y5, C1[4], r1);  r2 = fmaf(y5, C2[4], r2);  r3 = fmaf(y5, C3[4], r3);

            const long gbase = (long)b * (long)(NFREQ * F) + f;
            if (gbase + 0L*F < (long)fcap) __stcs(ob + f,       r0);
            if (gbase + 1L*F < (long)fcap) __stcs(ob + F + f,   r1);
            if (gbase + 2L*F < (long)fcap) __stcs(ob + 2*F + f, r2);
            if (gbase + 3L*F < (long)fcap) __stcs(ob + 3*F + f, r3);
        }
    }
}

} // namespace

extern "C" void kernel_launch(void* const* d_in, const int* in_sizes, int n_in,
                              void* d_out, int out_size)
{
    const float* x = (const float*)d_in[0];   // [64, 500000] float32
    const float* w = (const float*)d_in[1];   // [6] float32
    float* out     = (float*)d_out;           // [64, 4, 249997] float32 (real part)

    const long nx = (long)in_sizes[0];              // 32,000,000
    const int  L  = (int)(nx / Bc);                  // 500,000
    const int  F  = 1 + (L - 7) / 2;                 // 249,997

    const bool exact = ((long)out_size == (long)NFREQ * Bc * (long)F);
    const int  fullF = exact ? F : 0;

    const int blocks_x = (F + TILE - 1) / TILE;      // 123
    dim3 grid((unsigned)blocks_x, Bc);               // (123, 64)
    stft_re_kernel<<<grid, TPB>>>(x, w, out, L, F, fullF, out_size);
}

// round 17
// speedup vs baseline: 1.0626x; 1.0626x over previous
#include <cuda_runtime.h>
#include <cuda_bf16.h>
#include <cstdint>

// STFT (real part only): n_fft=7, hop=2, win_len=6 (w_pad[6]=0), onesided n_freq=4.
// ABI ground truth (rounds 9-14):
//   d_in[0] = x, 32,000,000 float32  ([64, 500000])
//   d_in[1] = w, 6 float32
//   d_out   = 63,999,232 float32 ([64,4,249997]) -- real part of the STFT.
// out[b][k][f] = sum_{n=0..5} x[b,2f+n]*w[n]*cos(2*pi*n*k/7)
//
// R17: R14 structure with EXPLICIT load batching -- all 12 LDG.64 issued into
// live registers before any compute/store, forcing per-thread MLP ~12 (R16
// showed ptxas won't widen the window on its own; regs stayed 32).

namespace {

constexpr int NFREQ = 4;
constexpr int Bc    = 64;
constexpr int FPT   = 4;               // frames per thread
constexpr int TPB   = 256;
constexpr int TILE  = TPB * FPT;       // 1024 frames per block

__global__ __launch_bounds__(TPB)
void stft_re_kernel(const float* __restrict__ x,
                    const float* __restrict__ w,
                    float* __restrict__ out,
                    int L, int F,
                    int fullF,     // == F when geometry exact (fast path), else 0
                    int fcap)      // float store cap for guarded path
{
    // cos(2*pi*(n*k mod 7)/7) for k=1..3, n=1..5 (n=0 -> 1; n=6 unused).
    const float C1[5] = { 0.623489802f, -0.222520934f, -0.900968868f, -0.900968868f, -0.222520934f };
    const float C2[5] = {-0.222520934f, -0.900968868f,  0.623489802f,  0.623489802f, -0.900968868f };
    const float C3[5] = {-0.900968868f,  0.623489802f, -0.222520934f, -0.222520934f,  0.623489802f };

    const int tid = threadIdx.x;
    const int b   = blockIdx.y;
    const int F0  = blockIdx.x * TILE;

    float wv[6];
    #pragma unroll
    for (int n = 0; n < 6; n++) wv[n] = w[n];

    const float2* __restrict__ X2 = reinterpret_cast<const float2*>(x) + (size_t)b * (size_t)(L >> 1);
    float* __restrict__ ob        = out + (size_t)b * (size_t)(NFREQ * F);

    if (F0 + TILE <= fullF) {
        // ---- fast path: batch ALL loads first (12 outstanding LDG.64) ----
        float2 A[FPT], C[FPT], E[FPT];
        #pragma unroll
        for (int j = 0; j < FPT; j++) {
            const int f = F0 + j * TPB + tid;
            A[j] = __ldg(X2 + f);
            C[j] = __ldg(X2 + f + 1);
            E[j] = __ldg(X2 + f + 2);
        }

        #pragma unroll
        for (int j = 0; j < FPT; j++) {
            const int f = F0 + j * TPB + tid;

            const float y0 = A[j].x * wv[0];
            const float y1 = A[j].y * wv[1];
            const float y2 = C[j].x * wv[2];
            const float y3 = C[j].y * wv[3];
            const float y4 = E[j].x * wv[4];
            const float y5 = E[j].y * wv[5];

            const float r0 = ((y0 + y1) + (y2 + y3)) + (y4 + y5);
            float r1 = y0, r2 = y0, r3 = y0;
            r1 = fmaf(y1, C1[0], r1);  r2 = fmaf(y1, C2[0], r2);  r3 = fmaf(y1, C3[0], r3);
            r1 = fmaf(y2, C1[1], r1);  r2 = fmaf(y2, C2[1], r2);  r3 = fmaf(y2, C3[1], r3);
            r1 = fmaf(y3, C1[2], r1);  r2 = fmaf(y3, C2[2], r2);  r3 = fmaf(y3, C3[2], r3);
            r1 = fmaf(y4, C1[3], r1);  r2 = fmaf(y4, C2[3], r2);  r3 = fmaf(y4, C3[3], r3);
            r1 = fmaf(y5, C1[4], r1);  r2 = fmaf(y5, C2[4], r2);  r3 = fmaf(y5, C3[4], r3);

            float* p = ob + f;
            __stcs(p, r0);  p += F;
            __stcs(p, r1);  p += F;
            __stcs(p, r2);  p += F;
            __stcs(p, r3);
        }
    } else {
        // ---- guarded path (tail block; whole grid if ABI mismatch) ----
        #pragma unroll
        for (int j = 0; j < FPT; j++) {
            const int f = F0 + j * TPB + tid;
            if (f >= F) continue;

            const float2 a = __ldg(X2 + f);
            const float2 c = __ldg(X2 + f + 1);   // floats <= 2(F-1)+3 < L
            const float2 e = __ldg(X2 + f + 2);   // floats <= 2(F-1)+5 < L

            const float y0 = a.x * wv[0];
            const float y1 = a.y * wv[1];
            const float y2 = c.x * wv[2];
            const float y3 = c.y * wv[3];
            const float y4 = e.x * wv[4];
            const float y5 = e.y * wv[5];

            const float r0 = ((y0 + y1) + (y2 + y3)) + (y4 + y5);
            float r1 = y0, r2 = y0, r3 = y0;
            r1 = fmaf(y1, C1[0], r1);  r2 = fmaf(y1, C2[0], r2);  r3 = fmaf(y1, C3[0], r3);
            r1 = fmaf(y2, C1[1], r1);  r2 = fmaf(y2, C2[1], r2);  r3 = fmaf(y2, C3[1], r3);
            r1 = fmaf(y3, C1[2], r1);  r2 = fmaf(y3, C2[2], r2);  r3 = fmaf(y3, C3[2], r3);
            r1 = fmaf(y4, C1[3], r1);  r2 = fmaf(y4, C2[3], r2);  r3 = fmaf(y4, C3[3], r3);
            r1 = fmaf(y5, C1[4], r1);  r2 = fmaf(y5, C2[4], r2);  r3 = fmaf(y5, C3[4], r3);

            const long gbase = (long)b * (long)(NFREQ * F) + f;
            if (gbase + 0L*F < (long)fcap) __stcs(ob + f,       r0);
            if (gbase + 1L*F < (long)fcap) __stcs(ob + F + f,   r1);
            if (gbase + 2L*F < (long)fcap) __stcs(ob + 2*F + f, r2);
            if (gbase + 3L*F < (long)fcap) __stcs(ob + 3*F + f, r3);
        }
    }
}

} // namespace

extern "C" void kernel_launch(void* const* d_in, const int* in_sizes, int n_in,
                              void* d_out, int out_size)
{
    const float* x = (const float*)d_in[0];   // [64, 500000] float32
    const float* w = (const float*)d_in[1];   // [6] float32
    float* out     = (float*)d_out;           // [64, 4, 249997] float32 (real part)

    const long nx = (long)in_sizes[0];              // 32,000,000
    const int  L  = (int)(nx / Bc);                  // 500,000
    const int  F  = 1 + (L - 7) / 2;                 // 249,997

    const bool exact = ((long)out_size == (long)NFREQ * Bc * (long)F);
    const int  fullF = exact ? F : 0;

    const int blocks_x = (F + TILE - 1) / TILE;      // 245
    dim3 grid((unsigned)blocks_x, Bc);               // (245, 64)
    stft_re_kernel<<<grid, TPB>>>(x, w, out, L, F, fullF, out_size);
}